// round 1
// baseline (speedup 1.0000x reference)
#include <cuda_runtime.h>

#define NN 100000
#define NE 1600000
#define FIN 256
#define FH 64
#define FC 16

// ---- scratch (device globals; no runtime allocation allowed) ----
__device__ float g_dinv[NN];                     // degree, then rsqrt(degree) in place
__device__ float g_h1[(size_t)NN * FH];          // x @ W1
__device__ float g_agg1[(size_t)NN * FH];        // layer-1 aggregated output (pre-relu)
__device__ float g_h2[(size_t)NN * FC];          // relu(agg1) @ W2
__device__ int   g_is64;                         // edge_index dtype flag

// ---------------------------------------------------------------
// dtype detection: int64 edge data read as int64 is always in [0, NN);
// int32 data misinterpreted as int64 packs two indices per word and is
// >= 2^32 unless the high index is exactly 0 (prob ~1e-5 per element).
__global__ void k_detect(const void* ei) {
    const long long* p = (const long long*)ei;
    int ok = 1;
    for (int i = 0; i < 64; i++) {
        long long v = p[i];
        if (v < 0 || v >= NN) { ok = 0; break; }
    }
    g_is64 = ok;
}

__device__ __forceinline__ int load_idx(const void* ei, int which, int e) {
    if (g_is64) return (int)((const long long*)ei)[(size_t)which * NE + e];
    else        return ((const int*)ei)[(size_t)which * NE + e];
}

// ---------------------------------------------------------------
__global__ void k_deg_init() {
    int i = blockIdx.x * blockDim.x + threadIdx.x;
    if (i < NN) g_dinv[i] = 1.0f;   // self-loop
}

__global__ void k_deg_accum(const void* __restrict__ ei) {
    int e = blockIdx.x * blockDim.x + threadIdx.x;
    if (e < NE) {
        int d = load_idx(ei, 1, e);
        atomicAdd(&g_dinv[d], 1.0f);
    }
}

__global__ void k_dinv() {
    int i = blockIdx.x * blockDim.x + threadIdx.x;
    if (i < NN) g_dinv[i] = rsqrtf(g_dinv[i]);   // deg >= 1 always
}

// ---------------------------------------------------------------
// GEMM1: h1[N,64] = x[N,256] @ W1[256,64]; also init agg1 = b1 + h1*dinv^2
__global__ __launch_bounds__(256, 2) void k_gemm1(const float* __restrict__ x,
                                                  const float* __restrict__ W1,
                                                  const float* __restrict__ b1) {
    __shared__ float Ws[128 * FH];   // 32 KB K-tile of W1
    int row = blockIdx.x * 256 + threadIdx.x;

    float acc[FH];
#pragma unroll
    for (int j = 0; j < FH; j++) acc[j] = 0.0f;

    for (int kt = 0; kt < FIN; kt += 128) {
        __syncthreads();
        {
            const float4* wsrc = (const float4*)(W1 + (size_t)kt * FH);
            float4* wdst = (float4*)Ws;
#pragma unroll
            for (int i = 0; i < 8; i++)
                wdst[threadIdx.x + i * 256] = wsrc[threadIdx.x + i * 256];
        }
        __syncthreads();

        if (row < NN) {
            const float4* xr = (const float4*)(x + (size_t)row * FIN + kt);
#pragma unroll
            for (int k4 = 0; k4 < 32; k4++) {
                float4 xv = xr[k4];
                const float4* w0 = (const float4*)&Ws[(k4 * 4 + 0) * FH];
                const float4* w1 = (const float4*)&Ws[(k4 * 4 + 1) * FH];
                const float4* w2 = (const float4*)&Ws[(k4 * 4 + 2) * FH];
                const float4* w3 = (const float4*)&Ws[(k4 * 4 + 3) * FH];
#pragma unroll
                for (int j4 = 0; j4 < 16; j4++) {
                    float4 a = w0[j4], b = w1[j4], c = w2[j4], d = w3[j4];
                    acc[4 * j4 + 0] += xv.x * a.x + xv.y * b.x + xv.z * c.x + xv.w * d.x;
                    acc[4 * j4 + 1] += xv.x * a.y + xv.y * b.y + xv.z * c.y + xv.w * d.y;
                    acc[4 * j4 + 2] += xv.x * a.z + xv.y * b.z + xv.z * c.z + xv.w * d.z;
                    acc[4 * j4 + 3] += xv.x * a.w + xv.y * b.w + xv.z * c.w + xv.w * d.w;
                }
            }
        }
    }

    if (row < NN) {
        float di = g_dinv[row];
        float d2 = di * di;
#pragma unroll
        for (int j = 0; j < FH; j += 4) {
            float4 h;
            h.x = acc[j]; h.y = acc[j + 1]; h.z = acc[j + 2]; h.w = acc[j + 3];
            *(float4*)&g_h1[(size_t)row * FH + j] = h;
            float4 ag;
            ag.x = h.x * d2 + b1[j];
            ag.y = h.y * d2 + b1[j + 1];
            ag.z = h.z * d2 + b1[j + 2];
            ag.w = h.w * d2 + b1[j + 3];
            *(float4*)&g_agg1[(size_t)row * FH + j] = ag;
        }
    }
}

// ---------------------------------------------------------------
__device__ __forceinline__ void red_add_v4(float* addr, float4 v) {
    asm volatile("red.global.add.v4.f32 [%0], {%1,%2,%3,%4};"
                 :: "l"(addr), "f"(v.x), "f"(v.y), "f"(v.z), "f"(v.w)
                 : "memory");
}

// scatter layer 1: 16 threads per edge, each moves 4 floats
__global__ __launch_bounds__(256) void k_scatter1(const void* __restrict__ ei) {
    int t = blockIdx.x * 256 + threadIdx.x;
    int e = t >> 4;
    int part = t & 15;
    if (e >= NE) return;
    int s = load_idx(ei, 0, e);
    int d = load_idx(ei, 1, e);
    float norm = g_dinv[s] * g_dinv[d];
    float4 v = *(const float4*)&g_h1[(size_t)s * FH + part * 4];
    v.x *= norm; v.y *= norm; v.z *= norm; v.w *= norm;
    red_add_v4(&g_agg1[(size_t)d * FH + part * 4], v);
}

// ---------------------------------------------------------------
// GEMM2: h2 = relu(agg1) @ W2[64,16]; init out = b2 + h2*dinv^2
__global__ __launch_bounds__(256) void k_gemm2(const float* __restrict__ W2,
                                               const float* __restrict__ b2,
                                               float* __restrict__ out) {
    __shared__ float Ws[FH * FC];   // 4 KB
    for (int i = threadIdx.x; i < FH * FC; i += 256) Ws[i] = W2[i];
    __syncthreads();

    int row = blockIdx.x * 256 + threadIdx.x;
    if (row >= NN) return;

    float acc[FC];
#pragma unroll
    for (int j = 0; j < FC; j++) acc[j] = 0.0f;

    const float4* ar = (const float4*)&g_agg1[(size_t)row * FH];
#pragma unroll
    for (int k4 = 0; k4 < 16; k4++) {
        float4 h4 = ar[k4];
        float hv[4];
        hv[0] = fmaxf(h4.x, 0.0f);
        hv[1] = fmaxf(h4.y, 0.0f);
        hv[2] = fmaxf(h4.z, 0.0f);
        hv[3] = fmaxf(h4.w, 0.0f);
#pragma unroll
        for (int kk = 0; kk < 4; kk++) {
            const float4* wr = (const float4*)&Ws[(k4 * 4 + kk) * FC];
#pragma unroll
            for (int j4 = 0; j4 < 4; j4++) {
                float4 w = wr[j4];
                acc[j4 * 4 + 0] += hv[kk] * w.x;
                acc[j4 * 4 + 1] += hv[kk] * w.y;
                acc[j4 * 4 + 2] += hv[kk] * w.z;
                acc[j4 * 4 + 3] += hv[kk] * w.w;
            }
        }
    }

    float di = g_dinv[row];
    float d2 = di * di;
#pragma unroll
    for (int j = 0; j < FC; j += 4) {
        float4 h;
        h.x = acc[j]; h.y = acc[j + 1]; h.z = acc[j + 2]; h.w = acc[j + 3];
        *(float4*)&g_h2[(size_t)row * FC + j] = h;
        float4 o;
        o.x = h.x * d2 + b2[j];
        o.y = h.y * d2 + b2[j + 1];
        o.z = h.z * d2 + b2[j + 2];
        o.w = h.w * d2 + b2[j + 3];
        *(float4*)&out[(size_t)row * FC + j] = o;
    }
}

// scatter layer 2: 4 threads per edge
__global__ __launch_bounds__(256) void k_scatter2(const void* __restrict__ ei,
                                                  float* __restrict__ out) {
    int t = blockIdx.x * 256 + threadIdx.x;
    int e = t >> 2;
    int part = t & 3;
    if (e >= NE) return;
    int s = load_idx(ei, 0, e);
    int d = load_idx(ei, 1, e);
    float norm = g_dinv[s] * g_dinv[d];
    float4 v = *(const float4*)&g_h2[(size_t)s * FC + part * 4];
    v.x *= norm; v.y *= norm; v.z *= norm; v.w *= norm;
    red_add_v4(&out[(size_t)d * FC + part * 4], v);
}

// ---------------------------------------------------------------
extern "C" void kernel_launch(void* const* d_in, const int* in_sizes, int n_in,
                              void* d_out, int out_size) {
    const float* x  = (const float*)d_in[0];
    const void*  ei = d_in[1];                 // int64 or int32, detected on device
    const float* W1 = (const float*)d_in[2];
    const float* b1 = (const float*)d_in[3];
    const float* W2 = (const float*)d_in[4];
    const float* b2 = (const float*)d_in[5];
    float* out = (float*)d_out;

    k_detect<<<1, 1>>>(ei);
    k_deg_init<<<(NN + 255) / 256, 256>>>();
    k_deg_accum<<<(NE + 255) / 256, 256>>>(ei);
    k_dinv<<<(NN + 255) / 256, 256>>>();
    k_gemm1<<<(NN + 255) / 256, 256>>>(x, W1, b1);
    {
        long long threads = (long long)NE * 16;
        k_scatter1<<<(unsigned)((threads + 255) / 256), 256>>>(ei);
    }
    k_gemm2<<<(NN + 255) / 256, 256>>>(W2, b2, out);
    {
        long long threads = (long long)NE * 4;
        k_scatter2<<<(unsigned)((threads + 255) / 256), 256>>>(ei, out);
    }
}